// round 2
// baseline (speedup 1.0000x reference)
#include <cuda_runtime.h>

// LSTM anomaly detector: B=4096, T=512, I=3, H=64.
// Persistent kernel: 128 blocks x 512 threads, 32 batch rows per block.
// Each thread owns one gate unit g (0..255) for 16 rows; W_hh row in registers.
// h in shared, c in registers, fused input projection + decoder.

#define BATCH 4096
#define TSTEPS 512
#define NIN 3
#define HD 64
#define NG 256            // 4*HD gate units
#define ROWS 32           // batch rows per block
#define NTHREADS 512
#define NBLOCKS (BATCH / ROWS)   // 128

__device__ __forceinline__ float fast_ex2(float x) {
    float y; asm("ex2.approx.f32 %0, %1;" : "=f"(y) : "f"(x)); return y;
}
__device__ __forceinline__ float fast_rcp(float x) {
    float y; asm("rcp.approx.f32 %0, %1;" : "=f"(y) : "f"(x)); return y;
}
// sigmoid(x) = 1 / (1 + 2^(-x*log2e))
__device__ __forceinline__ float sigmoid_(float x) {
    return fast_rcp(1.0f + fast_ex2(-1.4426950408889634f * x));
}
// tanh(x) = 1 - 2 / (2^(2x*log2e) + 1)
__device__ __forceinline__ float tanh_(float x) {
    float e = fast_ex2(2.8853900817779268f * x);
    return 1.0f - 2.0f * fast_rcp(e + 1.0f);
}

__global__ void __launch_bounds__(NTHREADS, 1)
lstm_kernel(const float* __restrict__ x,
            const float* __restrict__ W_ih,
            const float* __restrict__ W_hh,
            const float* __restrict__ b_ih,
            const float* __restrict__ b_hh,
            const float* __restrict__ W_dec,
            const float* __restrict__ b_dec,
            float* __restrict__ out)
{
    __shared__ __align__(16) float gates_s[ROWS][NG];   // 32 KB
    __shared__ __align__(16) float h_s[ROWS][HD];       // 8 KB
    __shared__ __align__(16) float4 x_s[2][ROWS];       // 1 KB (x padded to 4)
    __shared__ __align__(16) float wdec_s[NIN][HD];     // 768 B
    __shared__ float bdec_s[NIN];

    const int t    = threadIdx.x;
    const int g    = t & (NG - 1);       // gate unit this thread owns
    const int half = t >> 8;             // 0: rows 0..15, 1: rows 16..31
    const int row0 = blockIdx.x * ROWS;

    // --- one-time weight load ---
    float w[HD];
    #pragma unroll
    for (int j = 0; j < HD; j++) w[j] = W_hh[g * HD + j];
    const float wih0 = W_ih[g * NIN + 0];
    const float wih1 = W_ih[g * NIN + 1];
    const float wih2 = W_ih[g * NIN + 2];
    const float bsum = b_ih[g] + b_hh[g];

    if (t < NIN * HD) wdec_s[t / HD][t % HD] = W_dec[t];
    if (t < NIN)      bdec_s[t] = b_dec[t];

    // --- init state ---
    float c_reg[4];
    #pragma unroll
    for (int k = 0; k < 4; k++) c_reg[k] = 0.0f;
    for (int i = t; i < ROWS * HD; i += NTHREADS) ((float*)h_s)[i] = 0.0f;

    // preload x for step 0
    if (t < ROWS) {
        const float* xp = x + (size_t)(row0 + t) * TSTEPS * NIN;
        x_s[0][t] = make_float4(xp[0], xp[1], xp[2], 0.0f);
    }
    __syncthreads();

    for (int step = 0; step < TSTEPS; step++) {
        const int p = step & 1;

        // prefetch next step's x into registers (latency hidden under GEMM)
        float nx0 = 0.f, nx1 = 0.f, nx2 = 0.f;
        if (t < ROWS && step + 1 < TSTEPS) {
            const float* xp = x + (size_t)(row0 + t) * TSTEPS * NIN
                                + (size_t)(step + 1) * NIN;
            nx0 = xp[0]; nx1 = xp[1]; nx2 = xp[2];
        }

        // --- gate matvec: gates[r][g] = bsum + W_ih[g,:].x[r] + W_hh[g,:].h[r] ---
        const int rbase = half * 16;
        #pragma unroll 4
        for (int rr = 0; rr < 16; rr++) {
            const int r = rbase + rr;
            const float4 xv = x_s[p][r];
            float acc = bsum + wih0 * xv.x + wih1 * xv.y + wih2 * xv.z;
            const float4* h4 = (const float4*)h_s[r];
            #pragma unroll
            for (int j = 0; j < HD / 4; j++) {
                const float4 hv = h4[j];   // broadcast across the warp
                acc += w[4*j + 0] * hv.x;
                acc += w[4*j + 1] * hv.y;
                acc += w[4*j + 2] * hv.z;
                acc += w[4*j + 3] * hv.w;
            }
            gates_s[r][g] = acc;
        }
        __syncthreads();

        // --- activation: 2048 units / 512 threads = 4 units per thread (fixed map) ---
        #pragma unroll
        for (int k = 0; k < 4; k++) {
            const int idx = t + k * NTHREADS;
            const int r = idx >> 6, u = idx & 63;
            const float ig = sigmoid_(gates_s[r][u]);
            const float fg = sigmoid_(gates_s[r][u + 64]);
            const float gg = tanh_   (gates_s[r][u + 128]);
            const float og = sigmoid_(gates_s[r][u + 192]);
            const float c  = fg * c_reg[k] + ig * gg;
            c_reg[k] = c;
            h_s[r][u] = og * tanh_(c);
        }

        // stash prefetched x into the other buffer before the barrier
        if (t < ROWS && step + 1 < TSTEPS)
            x_s[p ^ 1][t] = make_float4(nx0, nx1, nx2, 0.0f);
        __syncthreads();

        // --- decoder: out[r, step, o] = W_dec[o,:] . h[r] + b_dec[o] ---
        if (t < ROWS * NIN) {
            const int r = t / NIN, o = t - r * NIN;
            float s = bdec_s[o];
            const float4* hr4 = (const float4*)h_s[r];
            const float4* wd4 = (const float4*)wdec_s[o];
            #pragma unroll
            for (int j = 0; j < HD / 4; j++) {
                const float4 a = hr4[j];
                const float4 b = wd4[j];
                s += a.x * b.x + a.y * b.y + a.z * b.z + a.w * b.w;
            }
            out[(size_t)(row0 + r) * TSTEPS * NIN + (size_t)step * NIN + o] = s;
        }
        // next iteration's GEMM only READS h_s/gates_s written before the barrier
    }
}

extern "C" void kernel_launch(void* const* d_in, const int* in_sizes, int n_in,
                              void* d_out, int out_size)
{
    const float* x     = (const float*)d_in[0];
    const float* W_ih  = (const float*)d_in[1];
    const float* W_hh  = (const float*)d_in[2];
    const float* b_ih  = (const float*)d_in[3];
    const float* b_hh  = (const float*)d_in[4];
    const float* W_dec = (const float*)d_in[5];
    const float* b_dec = (const float*)d_in[6];
    float* out = (float*)d_out;

    lstm_kernel<<<NBLOCKS, NTHREADS>>>(x, W_ih, W_hh, b_ih, b_hh, W_dec, b_dec, out);
}

// round 5
// speedup vs baseline: 1.0590x; 1.0590x over previous
#include <cuda_runtime.h>

// LSTM anomaly detector: B=4096, T=512, I=3, H=64.
// Persistent kernel: 128 blocks x 512 threads, 32 batch rows per block.
// Each thread owns one gate unit g (0..255) for 16 rows.
// R2: recurrent matvec via packed fma.rn.f32x2 (FFMA2) over the K dimension.
//     W_hh pairs {w[2j],w[2j+1]} in 64-bit regs; h pairs come free from LDS.128.

#define BATCH 4096
#define TSTEPS 512
#define NIN 3
#define HD 64
#define NG 256            // 4*HD gate units
#define ROWS 32           // batch rows per block
#define NTHREADS 512
#define NBLOCKS (BATCH / ROWS)   // 128

typedef unsigned long long u64;

__device__ __forceinline__ u64 fma2(u64 a, u64 b, u64 c) {
    u64 d;
    asm("fma.rn.f32x2 %0, %1, %2, %3;" : "=l"(d) : "l"(a), "l"(b), "l"(c));
    return d;
}
__device__ __forceinline__ float hsum2(u64 v) {
    float lo, hi;
    asm("mov.b64 {%0, %1}, %2;" : "=f"(lo), "=f"(hi) : "l"(v));
    return lo + hi;
}

__device__ __forceinline__ float fast_ex2(float x) {
    float y; asm("ex2.approx.f32 %0, %1;" : "=f"(y) : "f"(x)); return y;
}
__device__ __forceinline__ float fast_rcp(float x) {
    float y; asm("rcp.approx.f32 %0, %1;" : "=f"(y) : "f"(x)); return y;
}
__device__ __forceinline__ float sigmoid_(float x) {
    return fast_rcp(1.0f + fast_ex2(-1.4426950408889634f * x));
}
__device__ __forceinline__ float tanh_(float x) {
    float e = fast_ex2(2.8853900817779268f * x);
    return 1.0f - 2.0f * fast_rcp(e + 1.0f);
}

__global__ void __launch_bounds__(NTHREADS, 1)
lstm_kernel(const float* __restrict__ x,
            const float* __restrict__ W_ih,
            const float* __restrict__ W_hh,
            const float* __restrict__ b_ih,
            const float* __restrict__ b_hh,
            const float* __restrict__ W_dec,
            const float* __restrict__ b_dec,
            float* __restrict__ out)
{
    __shared__ __align__(16) float gates_s[ROWS][NG];   // 32 KB
    __shared__ __align__(16) float h_s[ROWS][HD];       // 8 KB
    __shared__ __align__(16) float4 x_s[2][ROWS];       // 1 KB (x padded to 4)
    __shared__ __align__(16) float wdec_s[NIN][HD];     // 768 B
    __shared__ float bdec_s[NIN];

    const int t    = threadIdx.x;
    const int g    = t & (NG - 1);       // gate unit this thread owns
    const int half = t >> 8;             // 0: rows 0..15, 1: rows 16..31
    const int row0 = blockIdx.x * ROWS;

    // --- one-time weight load: W_hh row g as 32 packed f32x2 pairs ---
    u64 w2[HD / 2];
    {
        const ulonglong2* wg = (const ulonglong2*)(W_hh + (size_t)g * HD);
        #pragma unroll
        for (int j = 0; j < HD / 4; j++) {
            ulonglong2 v = wg[j];
            w2[2 * j]     = v.x;
            w2[2 * j + 1] = v.y;
        }
    }
    const float wih0 = W_ih[g * NIN + 0];
    const float wih1 = W_ih[g * NIN + 1];
    const float wih2 = W_ih[g * NIN + 2];
    const float bsum = b_ih[g] + b_hh[g];

    if (t < NIN * HD) wdec_s[t / HD][t % HD] = W_dec[t];
    if (t < NIN)      bdec_s[t] = b_dec[t];

    // --- init state ---
    float c_reg[4];
    #pragma unroll
    for (int k = 0; k < 4; k++) c_reg[k] = 0.0f;
    for (int i = t; i < ROWS * HD; i += NTHREADS) ((float*)h_s)[i] = 0.0f;

    // preload x for step 0
    if (t < ROWS) {
        const float* xp = x + (size_t)(row0 + t) * TSTEPS * NIN;
        x_s[0][t] = make_float4(xp[0], xp[1], xp[2], 0.0f);
    }
    __syncthreads();

    for (int step = 0; step < TSTEPS; step++) {
        const int p = step & 1;

        // prefetch next step's x into registers (latency hidden under GEMM)
        float nx0 = 0.f, nx1 = 0.f, nx2 = 0.f;
        if (t < ROWS && step + 1 < TSTEPS) {
            const float* xp = x + (size_t)(row0 + t) * TSTEPS * NIN
                                + (size_t)(step + 1) * NIN;
            nx0 = xp[0]; nx1 = xp[1]; nx2 = xp[2];
        }

        // --- gate matvec: gates[r][g] = bsum + W_ih[g,:].x[r] + W_hh[g,:].h[r] ---
        const int rbase = half * 16;
        #pragma unroll 2
        for (int rr = 0; rr < 16; rr++) {
            const int r = rbase + rr;
            const float4 xv = x_s[p][r];
            const float accs = bsum + wih0 * xv.x + wih1 * xv.y + wih2 * xv.z;
            const ulonglong2* h2 = (const ulonglong2*)h_s[r];
            u64 acc2 = 0ull;   // {0.0f, 0.0f}
            #pragma unroll
            for (int j = 0; j < HD / 4; j++) {
                const ulonglong2 hv = h2[j];   // LDS.128, broadcast across warp
                acc2 = fma2(w2[2 * j],     hv.x, acc2);
                acc2 = fma2(w2[2 * j + 1], hv.y, acc2);
            }
            gates_s[r][g] = accs + hsum2(acc2);
        }
        __syncthreads();

        // --- activation: 2048 units / 512 threads = 4 units per thread (fixed map) ---
        #pragma unroll
        for (int k = 0; k < 4; k++) {
            const int idx = t + k * NTHREADS;
            const int r = idx >> 6, u = idx & 63;
            const float ig = sigmoid_(gates_s[r][u]);
            const float fg = sigmoid_(gates_s[r][u + 64]);
            const float gg = tanh_   (gates_s[r][u + 128]);
            const float og = sigmoid_(gates_s[r][u + 192]);
            const float c  = fg * c_reg[k] + ig * gg;
            c_reg[k] = c;
            h_s[r][u] = og * tanh_(c);
        }

        // stash prefetched x into the other buffer before the barrier
        if (t < ROWS && step + 1 < TSTEPS)
            x_s[p ^ 1][t] = make_float4(nx0, nx1, nx2, 0.0f);
        __syncthreads();

        // --- decoder: out[r, step, o] = W_dec[o,:] . h[r] + b_dec[o] ---
        if (t < ROWS * NIN) {
            const int r = t / NIN, o = t - r * NIN;
            float s = bdec_s[o];
            const float4* hr4 = (const float4*)h_s[r];
            const float4* wd4 = (const float4*)wdec_s[o];
            #pragma unroll
            for (int j = 0; j < HD / 4; j++) {
                const float4 a = hr4[j];
                const float4 b = wd4[j];
                s += a.x * b.x + a.y * b.y + a.z * b.z + a.w * b.w;
            }
            out[(size_t)(row0 + r) * TSTEPS * NIN + (size_t)step * NIN + o] = s;
        }
        // next iteration's GEMM only READS h_s/gates_s written before the barrier
    }
}

extern "C" void kernel_launch(void* const* d_in, const int* in_sizes, int n_in,
                              void* d_out, int out_size)
{
    const float* x     = (const float*)d_in[0];
    const float* W_ih  = (const float*)d_in[1];
    const float* W_hh  = (const float*)d_in[2];
    const float* b_ih  = (const float*)d_in[3];
    const float* b_hh  = (const float*)d_in[4];
    const float* W_dec = (const float*)d_in[5];
    const float* b_dec = (const float*)d_in[6];
    float* out = (float*)d_out;

    lstm_kernel<<<NBLOCKS, NTHREADS>>>(x, W_ih, W_hh, b_ih, b_hh, W_dec, b_dec, out);
}